// round 3
// baseline (speedup 1.0000x reference)
#include <cuda_runtime.h>
#include <math.h>

#define B_   64
#define NI_  2048
#define DI_  8
#define NC_  32
#define DC_  16

#define IBU  8                       // i's per k_u sub-block
#define ISG  16                      // i's per s1 sub-block
#define CHR  16                      // i-chunks per b in route
#define NBU  (NI_/IBU)               // 256 k_u blocks
#define NBS  ((NI_/ISG)*4)           // 512 s1 blocks (128 i-chunks x 4 c-groups)

// u layout: [b][i][d4][c][4]  -> float4 index = (b*NI+i)*128 + d4*32 + c
__device__ __align__(16) float g_u[B_*NI_*DC_*NC_];   // 256 MB
__device__ __align__(16) float g_s[B_*NC_*DC_];       // accumulator, zeroed after each use
__device__ __align__(16) float g_v0[B_*NC_*DC_];      // v1
__device__ __align__(16) float g_vr[B_*NC_*DC_];      // routing vector (v1, then v1+v2)

// ---------------------------------------------------------------------------
// k_front: fused launch.
//   blocks [0, NBS)        : s1 GEMM  s1[b,c,d] = sum_{i,f} x[b,i,f]*W[c,i,d,f]
//   blocks [NBS, NBS+NBU)  : u materialization in float4-friendly layout
// ---------------------------------------------------------------------------
__global__ __launch_bounds__(256) void k_front(const float* __restrict__ x,
                                               const float* __restrict__ W) {
    __shared__ __align__(16) float sh[16 * 512];   // 32 KB (s1 x-stage; k_u uses half)
    const int t = threadIdx.x;

    if (blockIdx.x < NBS) {
        // ---------------- s1 GEMM sub-kernel ----------------
        const int bid = blockIdx.x;
        const int ic  = bid & 127;          // i-chunk 0..127
        const int cg  = bid >> 7;           // c-group 0..3
        const int i0  = ic * ISG;

        // stage x transposed: sh[il*512 + f*64 + b]   (ISG=16 -> rem in [0,128))
        #pragma unroll
        for (int k = 0; k < 32; k++) {
            const int lin = t + 256 * k;                // 0..8191
            const int b = lin >> 7, rem = lin & 127;    // rem = il*8+f
            sh[(rem >> 3) * 512 + (rem & 7) * 64 + b] =
                x[b * (NI_ * DI_) + i0 * DI_ + rem];
        }
        __syncthreads();

        const int c  = cg * 8 + (t >> 5);   // output capsule (uniform per warp)
        const int bl = t & 31;              // lane = b (handles bl and bl+32)

        float acc0[DC_], acc1[DC_];
        #pragma unroll
        for (int d = 0; d < DC_; d++) { acc0[d] = 0.0f; acc1[d] = 0.0f; }

        for (int il = 0; il < ISG; il++) {
            const int i = i0 + il;
            float x0[DI_], x1[DI_];
            #pragma unroll
            for (int f = 0; f < DI_; f++) {
                x0[f] = sh[il * 512 + f * 64 + bl];
                x1[f] = sh[il * 512 + f * 64 + 32 + bl];
            }
            const float4* wrow = (const float4*)(W + ((c * NI_ + i) * DC_) * DI_);
            #pragma unroll
            for (int d = 0; d < DC_; d++) {
                const float4 wa = wrow[d * 2];        // uniform (broadcast) loads
                const float4 wb = wrow[d * 2 + 1];
                acc0[d] += x0[0]*wa.x + x0[1]*wa.y + x0[2]*wa.z + x0[3]*wa.w
                         + x0[4]*wb.x + x0[5]*wb.y + x0[6]*wb.z + x0[7]*wb.w;
                acc1[d] += x1[0]*wa.x + x1[1]*wa.y + x1[2]*wa.z + x1[3]*wa.w
                         + x1[4]*wb.x + x1[5]*wb.y + x1[6]*wb.z + x1[7]*wb.w;
            }
        }
        #pragma unroll
        for (int d = 0; d < DC_; d++) {
            atomicAdd(&g_s[(bl * NC_ + c) * DC_ + d], acc0[d]);
            atomicAdd(&g_s[((bl + 32) * NC_ + c) * DC_ + d], acc1[d]);
        }
    } else {
        // ---------------- u materialization sub-kernel ----------------
        const int i0 = (blockIdx.x - NBS) * IBU;

        // stage x: sh[il*512 + b*8 + f]   (IBU=8 -> rem = il*8+f in [0,64))
        #pragma unroll
        for (int k = 0; k < 16; k++) {
            const int lin = t + 256 * k;                // 0..4095
            const int b = lin >> 6, rem = lin & 63;     // FIX: was >>7 / &127
            sh[(rem >> 3) * 512 + b * 8 + (rem & 7)] =
                x[b * (NI_ * DI_) + i0 * DI_ + rem];
        }
        __syncthreads();

        const int w  = t >> 5, c = t & 31;
        const int d4 = w & 3, bh = w >> 2;
        float4* __restrict__ u4 = (float4*)g_u;

        for (int il = 0; il < IBU; il++) {
            const int i = i0 + il;
            // W[c,i,d4*4..+3, 0..7] -> 32 contiguous floats
            float wr[32];
            const float4* wp = (const float4*)(W + ((c * NI_ + i) * DC_ + d4 * 4) * DI_);
            #pragma unroll
            for (int j = 0; j < 8; j++) {
                const float4 v = wp[j];
                wr[4*j] = v.x; wr[4*j+1] = v.y; wr[4*j+2] = v.z; wr[4*j+3] = v.w;
            }
            #pragma unroll 4
            for (int blp = 0; blp < 32; blp++) {
                const int b = bh * 32 + blp;
                const float4 xa = *(const float4*)&sh[il * 512 + b * 8];
                const float4 xb = *(const float4*)&sh[il * 512 + b * 8 + 4];
                float4 acc;
                acc.x = xa.x*wr[0]  + xa.y*wr[1]  + xa.z*wr[2]  + xa.w*wr[3]
                      + xb.x*wr[4]  + xb.y*wr[5]  + xb.z*wr[6]  + xb.w*wr[7];
                acc.y = xa.x*wr[8]  + xa.y*wr[9]  + xa.z*wr[10] + xa.w*wr[11]
                      + xb.x*wr[12] + xb.y*wr[13] + xb.z*wr[14] + xb.w*wr[15];
                acc.z = xa.x*wr[16] + xa.y*wr[17] + xa.z*wr[18] + xa.w*wr[19]
                      + xb.x*wr[20] + xb.y*wr[21] + xb.z*wr[22] + xb.w*wr[23];
                acc.w = xa.x*wr[24] + xa.y*wr[25] + xa.z*wr[26] + xa.w*wr[27]
                      + xb.x*wr[28] + xb.y*wr[29] + xb.z*wr[30] + xb.w*wr[31];
                u4[(b * NI_ + i) * 128 + d4 * 32 + c] = acc;
            }
        }
    }
}

// ---------------------------------------------------------------------------
// k_route: fused agree -> softmax -> s-accumulate pass over u.
//   logits[c] = NI * <u[b,c,i,:], vr[b,c,:]>   (vr = v1 or v1+v2)
// lane = c; 4x LDG.128 per i; warp softmax; block reduce + atomics.
// ---------------------------------------------------------------------------
__global__ __launch_bounds__(256) void k_route() {
    __shared__ float s_sh[8 * 512];   // 16 KB
    const int chunk = blockIdx.x;     // 0..CHR-1
    const int b     = blockIdx.y;     // 0..63
    const int w = threadIdx.x >> 5, c = threadIdx.x & 31;
    const int IPW = NI_ / CHR / 8;    // 16
    const int i0 = chunk * (NI_ / CHR) + w * IPW;

    const float4* vr4 = (const float4*)g_vr + (b * NC_ + c) * 4;
    const float4 vr0 = vr4[0], vr1 = vr4[1], vr2 = vr4[2], vr3 = vr4[3];

    float4 s0 = {0,0,0,0}, s1 = {0,0,0,0}, s2 = {0,0,0,0}, s3 = {0,0,0,0};
    const float4* __restrict__ u4 = (const float4*)g_u;

    #pragma unroll 2
    for (int ii = 0; ii < IPW; ii++) {
        const int base = (b * NI_ + (i0 + ii)) * 128 + c;
        const float4 u0 = u4[base];
        const float4 u1 = u4[base + 32];
        const float4 u2 = u4[base + 64];
        const float4 u3 = u4[base + 96];

        float a = u0.x*vr0.x + u0.y*vr0.y + u0.z*vr0.z + u0.w*vr0.w
                + u1.x*vr1.x + u1.y*vr1.y + u1.z*vr1.z + u1.w*vr1.w
                + u2.x*vr2.x + u2.y*vr2.y + u2.z*vr2.z + u2.w*vr2.w
                + u3.x*vr3.x + u3.y*vr3.y + u3.z*vr3.z + u3.w*vr3.w;
        float logit = (float)NI_ * a;

        float m = logit;
        #pragma unroll
        for (int off = 16; off > 0; off >>= 1)
            m = fmaxf(m, __shfl_xor_sync(0xFFFFFFFFu, m, off));
        float e = __expf(logit - m);
        float sum = e;
        #pragma unroll
        for (int off = 16; off > 0; off >>= 1)
            sum += __shfl_xor_sync(0xFFFFFFFFu, sum, off);
        const float coef = e / sum;

        s0.x = fmaf(coef, u0.x, s0.x); s0.y = fmaf(coef, u0.y, s0.y);
        s0.z = fmaf(coef, u0.z, s0.z); s0.w = fmaf(coef, u0.w, s0.w);
        s1.x = fmaf(coef, u1.x, s1.x); s1.y = fmaf(coef, u1.y, s1.y);
        s1.z = fmaf(coef, u1.z, s1.z); s1.w = fmaf(coef, u1.w, s1.w);
        s2.x = fmaf(coef, u2.x, s2.x); s2.y = fmaf(coef, u2.y, s2.y);
        s2.z = fmaf(coef, u2.z, s2.z); s2.w = fmaf(coef, u2.w, s2.w);
        s3.x = fmaf(coef, u3.x, s3.x); s3.y = fmaf(coef, u3.y, s3.y);
        s3.z = fmaf(coef, u3.z, s3.z); s3.w = fmaf(coef, u3.w, s3.w);
    }

    // partials -> shared [w][d*32+c]
    const int sb = w * 512;
    s_sh[sb +  0*32 + c] = s0.x; s_sh[sb +  1*32 + c] = s0.y;
    s_sh[sb +  2*32 + c] = s0.z; s_sh[sb +  3*32 + c] = s0.w;
    s_sh[sb +  4*32 + c] = s1.x; s_sh[sb +  5*32 + c] = s1.y;
    s_sh[sb +  6*32 + c] = s1.z; s_sh[sb +  7*32 + c] = s1.w;
    s_sh[sb +  8*32 + c] = s2.x; s_sh[sb +  9*32 + c] = s2.y;
    s_sh[sb + 10*32 + c] = s2.z; s_sh[sb + 11*32 + c] = s2.w;
    s_sh[sb + 12*32 + c] = s3.x; s_sh[sb + 13*32 + c] = s3.y;
    s_sh[sb + 14*32 + c] = s3.z; s_sh[sb + 15*32 + c] = s3.w;
    __syncthreads();

    #pragma unroll
    for (int r = 0; r < 2; r++) {
        const int idx = threadIdx.x + r * 256;     // d*32 + c
        float acc = 0.0f;
        #pragma unroll
        for (int ww = 0; ww < 8; ww++) acc += s_sh[ww * 512 + idx];
        const int cc = idx & 31, dd = idx >> 5;
        atomicAdd(&g_s[(b * NC_ + cc) * DC_ + dd], acc);
    }
}

// ---------------------------------------------------------------------------
// squash: v = (|s|^2/(1+|s|^2)) * s / sqrt(|s|^2+eps). Zeroes g_s for next pass.
//   mode 1: v1 -> g_v0 and g_vr           (s scaled by 1/NC: uniform coupling)
//   mode 2: v2 -> g_vr = g_v0 + v2
//   mode 3: v3 -> out
// ---------------------------------------------------------------------------
__global__ void k_squash(int mode, float* __restrict__ out) {
    const int t = blockIdx.x * blockDim.x + threadIdx.x;
    if (t >= B_ * NC_) return;
    float* sp = g_s + t * DC_;
    const float scale = (mode == 1) ? (1.0f / (float)NC_) : 1.0f;
    float s[DC_];
    float sq = 0.0f;
    #pragma unroll
    for (int d = 0; d < DC_; d++) {
        s[d] = sp[d] * scale;
        sq += s[d] * s[d];
        sp[d] = 0.0f;
    }
    const float f2 = (sq / (1.0f + sq)) * rsqrtf(sq + 1e-7f);
    if (mode == 1) {
        #pragma unroll
        for (int d = 0; d < DC_; d++) {
            const float v = s[d] * f2;
            g_v0[t * DC_ + d] = v;
            g_vr[t * DC_ + d] = v;
        }
    } else if (mode == 2) {
        #pragma unroll
        for (int d = 0; d < DC_; d++)
            g_vr[t * DC_ + d] = g_v0[t * DC_ + d] + s[d] * f2;
    } else {
        #pragma unroll
        for (int d = 0; d < DC_; d++)
            out[t * DC_ + d] = s[d] * f2;
    }
}

// ---------------------------------------------------------------------------
extern "C" void kernel_launch(void* const* d_in, const int* in_sizes, int n_in,
                              void* d_out, int out_size) {
    const float* x = (const float*)d_in[0];
    const float* W = (const float*)d_in[1];
    if (n_in >= 2 && in_sizes[0] == NC_ * NI_ * DC_ * DI_) {  // defensive order swap
        const float* tmp = x; x = W; W = tmp;
    }
    float* out = (float*)d_out;

    // u materialization + s1 GEMM fused in one launch (overlap store- and fma-bound work)
    k_front<<<NBS + NBU, 256>>>(x, W);
    k_squash<<<8, 256>>>(1, nullptr);            // v1 -> g_v0, g_vr

    k_route<<<dim3(CHR, B_), 256>>>();           // pass 2: logits = NI*<u,v1>
    k_squash<<<8, 256>>>(2, nullptr);            // g_vr = v1 + v2

    k_route<<<dim3(CHR, B_), 256>>>();           // pass 3: logits = NI*<u,v1+v2>
    k_squash<<<8, 256>>>(3, out);                // v3 -> out
}